// round 13
// baseline (speedup 1.0000x reference)
#include <cuda_runtime.h>
#include <cuda_bf16.h>
#include <math.h>
#include <stdint.h>

#define E_DIM 1024
#define S_DIM 2048
#define B_DIM 2
#define H_DIM 16
#define NROWS (B_DIM * S_DIM)   // 4096

// ---------------- scratch (no allocations allowed) ----------------
__device__ float g_x2 [(size_t)NROWS * E_DIM];
// bf16 hi/lo activation buffers
__device__ __align__(16) unsigned short g_hh[(size_t)NROWS * E_DIM];
__device__ __align__(16) unsigned short g_hl[(size_t)NROWS * E_DIM];
__device__ __align__(16) unsigned short g_qkvh[(size_t)NROWS * 3 * E_DIM];
__device__ __align__(16) unsigned short g_qkvl[(size_t)NROWS * 3 * E_DIM];
__device__ __align__(16) unsigned short g_oh[(size_t)NROWS * E_DIM];
__device__ __align__(16) unsigned short g_ol[(size_t)NROWS * E_DIM];
__device__ __align__(16) unsigned short g_mh[(size_t)NROWS * 4 * E_DIM];
__device__ __align__(16) unsigned short g_ml[(size_t)NROWS * 4 * E_DIM];
// bf16 hi/lo weights
__device__ __align__(16) unsigned short g_winh [(size_t)3*E_DIM*E_DIM];
__device__ __align__(16) unsigned short g_winl [(size_t)3*E_DIM*E_DIM];
__device__ __align__(16) unsigned short g_wouth[(size_t)E_DIM*E_DIM];
__device__ __align__(16) unsigned short g_woutl[(size_t)E_DIM*E_DIM];
__device__ __align__(16) unsigned short g_wfch [(size_t)4*E_DIM*E_DIM];
__device__ __align__(16) unsigned short g_wfcl [(size_t)4*E_DIM*E_DIM];
__device__ __align__(16) unsigned short g_wprh [(size_t)4*E_DIM*E_DIM];
__device__ __align__(16) unsigned short g_wprl [(size_t)4*E_DIM*E_DIM];

// ================= helpers =================
__device__ __forceinline__ uint32_t smem_u32(const void* p) {
    uint32_t a;
    asm("{ .reg .u64 t; cvta.to.shared.u64 t, %1; cvt.u32.u64 %0, t; }"
        : "=r"(a) : "l"(p));
    return a;
}

__device__ __forceinline__ void ldsm4(uint32_t* r, uint32_t addr) {
    asm volatile("ldmatrix.sync.aligned.m8n8.x4.shared.b16 {%0,%1,%2,%3}, [%4];"
        : "=r"(r[0]), "=r"(r[1]), "=r"(r[2]), "=r"(r[3]) : "r"(addr));
}

__device__ __forceinline__ void ldsm4t(uint32_t* r, uint32_t addr) {
    asm volatile("ldmatrix.sync.aligned.m8n8.x4.trans.shared.b16 {%0,%1,%2,%3}, [%4];"
        : "=r"(r[0]), "=r"(r[1]), "=r"(r[2]), "=r"(r[3]) : "r"(addr));
}

__device__ __forceinline__ void mma16816(float* d, const uint32_t* a, const uint32_t* b) {
    asm volatile(
        "mma.sync.aligned.m16n8k16.row.col.f32.bf16.bf16.f32 "
        "{%0,%1,%2,%3}, {%4,%5,%6,%7}, {%8,%9}, {%0,%1,%2,%3};"
        : "+f"(d[0]), "+f"(d[1]), "+f"(d[2]), "+f"(d[3])
        : "r"(a[0]), "r"(a[1]), "r"(a[2]), "r"(a[3]), "r"(b[0]), "r"(b[1]));
}

#define CPA16(dst, src) \
    asm volatile("cp.async.cg.shared.global [%0], [%1], 16;" \
        :: "r"(dst), "l"(src) : "memory")
#define CPC() asm volatile("cp.async.commit_group;" ::: "memory")
#define CPW(n) asm volatile("cp.async.wait_group %0;" :: "n"(n) : "memory")

__device__ __forceinline__ void cvt8(float4 v0, float4 v1, uint4& hi, uint4& lo) {
    float x[8] = {v0.x, v0.y, v0.z, v0.w, v1.x, v1.y, v1.z, v1.w};
    uint32_t h[4], l[4];
    #pragma unroll
    for (int i = 0; i < 4; i++) {
        __nv_bfloat16 a = __float2bfloat16_rn(x[2*i]);
        __nv_bfloat16 b = __float2bfloat16_rn(x[2*i+1]);
        __nv_bfloat16 c = __float2bfloat16_rn(x[2*i]   - __bfloat162float(a));
        __nv_bfloat16 d = __float2bfloat16_rn(x[2*i+1] - __bfloat162float(b));
        h[i] = (uint32_t)__bfloat16_as_ushort(a) | ((uint32_t)__bfloat16_as_ushort(b) << 16);
        l[i] = (uint32_t)__bfloat16_as_ushort(c) | ((uint32_t)__bfloat16_as_ushort(d) << 16);
    }
    hi = make_uint4(h[0], h[1], h[2], h[3]);
    lo = make_uint4(l[0], l[1], l[2], l[3]);
}

__device__ __forceinline__ void packhl(float a, float b, uint32_t& hi, uint32_t& lo) {
    __nv_bfloat16 ah = __float2bfloat16_rn(a);
    __nv_bfloat16 bh = __float2bfloat16_rn(b);
    __nv_bfloat16 al = __float2bfloat16_rn(a - __bfloat162float(ah));
    __nv_bfloat16 bl = __float2bfloat16_rn(b - __bfloat162float(bh));
    hi = (uint32_t)__bfloat16_as_ushort(ah) | ((uint32_t)__bfloat16_as_ushort(bh) << 16);
    lo = (uint32_t)__bfloat16_as_ushort(al) | ((uint32_t)__bfloat16_as_ushort(bl) << 16);
}

// ---------------- merged weight fp32 -> bf16 hi/lo (one launch) ----------------
#define CW_N0 393216                       // w_in   3M/8
#define CW_N1 (CW_N0 + 131072)             // w_out  +1M/8
#define CW_N2 (CW_N1 + 524288)             // w_fc   +4M/8
#define CW_N3 (CW_N2 + 524288)             // w_proj +4M/8

__global__ __launch_bounds__(256) void cvtw_all_kernel(
    const float* __restrict__ s0, const float* __restrict__ s1,
    const float* __restrict__ s2, const float* __restrict__ s3,
    unsigned short* __restrict__ h0, unsigned short* __restrict__ l0,
    unsigned short* __restrict__ h1, unsigned short* __restrict__ l1,
    unsigned short* __restrict__ h2, unsigned short* __restrict__ l2,
    unsigned short* __restrict__ h3, unsigned short* __restrict__ l3)
{
    for (int i = blockIdx.x * blockDim.x + threadIdx.x; i < CW_N3;
         i += gridDim.x * blockDim.x) {
        const float* src; unsigned short *dh, *dl; int j;
        if (i < CW_N0)      { src = s0; dh = h0; dl = l0; j = i; }
        else if (i < CW_N1) { src = s1; dh = h1; dl = l1; j = i - CW_N0; }
        else if (i < CW_N2) { src = s2; dh = h2; dl = l2; j = i - CW_N1; }
        else                { src = s3; dh = h3; dl = l3; j = i - CW_N2; }
        float4 v0 = *(const float4*)(src + (size_t)j * 8);
        float4 v1 = *(const float4*)(src + (size_t)j * 8 + 4);
        uint4 h, l;
        cvt8(v0, v1, h, l);
        ((uint4*)dh)[j] = h;
        ((uint4*)dl)[j] = l;
    }
}

// ---------------- LayerNorm -> bf16 hi/lo ----------------
__global__ __launch_bounds__(256) void ln_kernel(const float* __restrict__ x,
                                                 unsigned short* __restrict__ yh,
                                                 unsigned short* __restrict__ yl)
{
    int row = blockIdx.x;
    int tid = threadIdx.x;
    const float* xr = x + (size_t)row * E_DIM;

    float4 v = *(const float4*)(xr + tid * 4);
    float s  = v.x + v.y + v.z + v.w;
    float ss = v.x*v.x + v.y*v.y + v.z*v.z + v.w*v.w;

    #pragma unroll
    for (int off = 16; off > 0; off >>= 1) {
        s  += __shfl_xor_sync(0xffffffffu, s,  off);
        ss += __shfl_xor_sync(0xffffffffu, ss, off);
    }

    __shared__ float rs[8], rss[8], stat[2];
    int wid = tid >> 5, lane = tid & 31;
    if (lane == 0) { rs[wid] = s; rss[wid] = ss; }
    __syncthreads();
    if (tid == 0) {
        float t = 0.f, tt = 0.f;
        #pragma unroll
        for (int i = 0; i < 8; i++) { t += rs[i]; tt += rss[i]; }
        float mean = t * (1.0f / E_DIM);
        float var  = tt * (1.0f / E_DIM) - mean * mean;
        stat[0] = mean;
        stat[1] = rsqrtf(var + 1e-5f);
    }
    __syncthreads();
    float mean = stat[0], rstd = stat[1];
    float o0 = (v.x - mean) * rstd, o1 = (v.y - mean) * rstd;
    float o2 = (v.z - mean) * rstd, o3 = (v.w - mean) * rstd;
    uint32_t h0, l0, h1, l1;
    packhl(o0, o1, h0, l0);
    packhl(o2, o3, h1, l1);
    uint2 hh = make_uint2(h0, h1), ll = make_uint2(l0, l1);
    *(uint2*)(yh + (size_t)row * E_DIM + tid * 4) = hh;
    *(uint2*)(yl + (size_t)row * E_DIM + tid * 4) = ll;
}

// ================= bf16x3 GEMM, cp.async pipeline (proven) =================
#define F_BIAS  1
#define F_RELU  2
#define F_RES   4
#define F_OUTBF 8

#define GB_TILE  10240
#define GB_STAGE (4 * GB_TILE)
#define GB_SMEM  (2 * GB_STAGE)

template<int FLAGS>
__global__ __launch_bounds__(256, 2)
void gemm_bf16_kernel(const unsigned short* __restrict__ Ah,
                      const unsigned short* __restrict__ Al,
                      const unsigned short* __restrict__ Bh,
                      const unsigned short* __restrict__ Bl,
                      const float* __restrict__ bias, const float* __restrict__ res,
                      float* __restrict__ C,
                      unsigned short* __restrict__ Ch, unsigned short* __restrict__ Cl,
                      int M, int N, int K)
{
    extern __shared__ __align__(16) char smem[];
    uint32_t sb = smem_u32(smem);

    int tid = threadIdx.x;
    int lane = tid & 31, wid = tid >> 5;
    int wm = wid >> 1, wn = wid & 1;
    int bn = blockIdx.x, bm = blockIdx.y;

    int r0 = tid >> 2, c0 = tid & 3;
    uint32_t so = (uint32_t)(r0 * 80 + c0 * 16);
    size_t goff = (size_t)r0 * K + c0 * 8;
    const unsigned short* pA0 = Ah + (size_t)(bm * 128) * K + goff;
    const unsigned short* pL0 = Al + (size_t)(bm * 128) * K + goff;
    const unsigned short* pB0 = Bh + (size_t)(bn * 128) * K + goff;
    const unsigned short* pX0 = Bl + (size_t)(bn * 128) * K + goff;
    size_t half = (size_t)64 * K;

    uint32_t rpA = (uint32_t)((wm * 32 + (lane & 15)) * 80 + (lane >> 4) * 16);
    int g = lane >> 3, l8 = lane & 7;
    uint32_t rpB = (uint32_t)((wn * 64 + l8 + (g >> 1) * 8) * 80 + (g & 1) * 16);

    float acc[2][8][4];
    #pragma unroll
    for (int mt = 0; mt < 2; mt++)
        #pragma unroll
        for (int nt = 0; nt < 8; nt++)
            #pragma unroll
            for (int i = 0; i < 4; i++) acc[mt][nt][i] = 0.f;

    int nch = K >> 5;

    #define GB_ISSUE(kc) do {                                            \
        if ((kc) < nch) {                                                \
            uint32_t sa = sb + (uint32_t)((kc) & 1) * GB_STAGE;          \
            int off = (kc) * 32;                                         \
            CPA16(sa + so,                        pA0 + off);            \
            CPA16(sa + so + 5120,                 pA0 + half + off);     \
            CPA16(sa + GB_TILE + so,              pL0 + off);            \
            CPA16(sa + GB_TILE + so + 5120,       pL0 + half + off);     \
            CPA16(sa + 2*GB_TILE + so,            pB0 + off);            \
            CPA16(sa + 2*GB_TILE + so + 5120,     pB0 + half + off);     \
            CPA16(sa + 3*GB_TILE + so,            pX0 + off);            \
            CPA16(sa + 3*GB_TILE + so + 5120,     pX0 + half + off);     \
        }                                                                \
        CPC();                                                           \
    } while (0)

    GB_ISSUE(0);
    GB_ISSUE(1);

    for (int kc = 0; kc < nch; kc++) {
        CPW(1);
        __syncthreads();

        uint32_t base = sb + (uint32_t)(kc & 1) * GB_STAGE;
        uint32_t aHi = base, aLo = base + GB_TILE;
        uint32_t bHi = base + 2*GB_TILE, bLo = base + 3*GB_TILE;

        #pragma unroll
        for (int k16 = 0; k16 < 2; k16++) {
            uint32_t ko = (uint32_t)k16 * 32;
            uint32_t ah[8], ax[8], bb[16];

            ldsm4(ah + 0, aHi + rpA + ko);
            ldsm4(ah + 4, aHi + rpA + 1280 + ko);
            ldsm4(ax + 0, aLo + rpA + ko);
            ldsm4(ax + 4, aLo + rpA + 1280 + ko);
            #pragma unroll
            for (int i = 0; i < 4; i++)
                ldsm4(bb + i*4, bHi + rpB + (uint32_t)i*1280 + ko);
            #pragma unroll
            for (int mt = 0; mt < 2; mt++)
                #pragma unroll
                for (int nt = 0; nt < 8; nt++)
                    mma16816(acc[mt][nt], ah + mt*4, bb + nt*2);
            #pragma unroll
            for (int mt = 0; mt < 2; mt++)
                #pragma unroll
                for (int nt = 0; nt < 8; nt++)
                    mma16816(acc[mt][nt], ax + mt*4, bb + nt*2);
            #pragma unroll
            for (int i = 0; i < 4; i++)
                ldsm4(bb + i*4, bLo + rpB + (uint32_t)i*1280 + ko);
            #pragma unroll
            for (int mt = 0; mt < 2; mt++)
                #pragma unroll
                for (int nt = 0; nt < 8; nt++)
                    mma16816(acc[mt][nt], ah + mt*4, bb + nt*2);
        }

        __syncthreads();
        GB_ISSUE(kc + 2);
    }
    #undef GB_ISSUE

    #pragma unroll
    for (int mt = 0; mt < 2; mt++) {
        int gr0 = bm*128 + wm*32 + mt*16 + (lane >> 2);
        #pragma unroll
        for (int nt = 0; nt < 8; nt++) {
            int gc = bn*128 + wn*64 + nt*8 + (lane & 3)*2;
            #pragma unroll
            for (int hfl = 0; hfl < 2; hfl++) {
                int row = gr0 + hfl*8;
                float v0 = acc[mt][nt][hfl*2+0];
                float v1 = acc[mt][nt][hfl*2+1];
                if (FLAGS & F_BIAS) {
                    v0 += __ldg(bias + gc);
                    v1 += __ldg(bias + gc + 1);
                }
                if (FLAGS & F_RES) {
                    float2 rr = *(const float2*)(res + (size_t)row * N + gc);
                    v0 += rr.x; v1 += rr.y;
                }
                if (FLAGS & F_RELU) { v0 = fmaxf(v0, 0.f); v1 = fmaxf(v1, 0.f); }
                if (FLAGS & F_OUTBF) {
                    uint32_t h, l;
                    packhl(v0, v1, h, l);
                    *(uint32_t*)(Ch + (size_t)row * N + gc) = h;
                    *(uint32_t*)(Cl + (size_t)row * N + gc) = l;
                } else {
                    float2 o = make_float2(v0, v1);
                    *(float2*)(C + (size_t)row * N + gc) = o;
                }
            }
        }
    }
}

// ================= Flash attention: bf16 hi/lo in, cp.async 3-stage, occ 2 =================
#define FST_TIL  9216                 // 64*144
#define FST_STG  (4 * FST_TIL)        // 36864
#define FST_SMEM (3 * FST_STG)        // 110592; x2 CTAs = 221184 <= 228KB

__global__ __launch_bounds__(256, 2)
void flash_mma_kernel(const unsigned short* __restrict__ qh_g,
                      const unsigned short* __restrict__ ql_g,
                      unsigned short* __restrict__ oh,
                      unsigned short* __restrict__ ol)
{
    extern __shared__ __align__(16) char smf[];
    uint32_t sb  = smem_u32(smf);

    int tid = threadIdx.x, lane = tid & 31, wid = tid >> 5;
    int qi = (int)gridDim.x - 1 - (int)blockIdx.x;   // longest CTAs first
    int bh = blockIdx.y;
    int b = bh >> 4, h = bh & 15;

    const int QKV_W = 3 * E_DIM;   // 3072
    size_t rowbase = (size_t)b * S_DIM;

    // ---- stage Q (hi/lo) through stage-0/1 smem, build register fragments ----
    {
        int r = tid >> 1, ce = (tid & 1) * 32;
        const unsigned short* sh = qh_g + (rowbase + qi*128 + r) * QKV_W + h*64 + ce;
        const unsigned short* sl = ql_g + (rowbase + qi*128 + r) * QKV_W + h*64 + ce;
        uint32_t d = sb + (uint32_t)(r*144 + ce*2);
        #pragma unroll
        for (int k = 0; k < 4; k++) {
            CPA16(d + k*16,         sh + k*8);
            CPA16(d + 18432 + k*16, sl + k*8);
        }
        CPC(); CPW(0);
    }
    __syncthreads();

    uint32_t qh[4][4], ql[4][4];
    {
        uint32_t ra = sb + (uint32_t)((wid*16 + (lane & 15))*144 + (lane >> 4)*16);
        #pragma unroll
        for (int ks = 0; ks < 4; ks++) {
            ldsm4(qh[ks], ra + ks*32);
            ldsm4(ql[ks], ra + 18432 + ks*32);
        }
    }
    __syncthreads();   // Q staging done before pipeline overwrites stage 0

    float oacc[8][4];
    #pragma unroll
    for (int nt = 0; nt < 8; nt++)
        #pragma unroll
        for (int i = 0; i < 4; i++) oacc[nt][i] = 0.f;
    float rm0 = -1e30f, rm1 = -1e30f, rl0 = 0.f, rl1 = 0.f;

    int g = lane >> 3, l8 = lane & 7;
    uint32_t rpB = (uint32_t)((l8 + (g >> 1)*8)*144 + (g & 1)*16);
    uint32_t rpV = (uint32_t)((lane & 15)*144 + (lane >> 4)*16);

    int rowlim = qi*128 + wid*16 + 15;
    int nj = 2*qi + 2;

    int rkv = tid >> 2, ckv = tid & 3;
    uint32_t skv = (uint32_t)(rkv*144 + ckv*32);
    const unsigned short* kh0 = qh_g + (rowbase + rkv) * QKV_W + E_DIM   + h*64 + ckv*16;
    const unsigned short* kl0 = ql_g + (rowbase + rkv) * QKV_W + E_DIM   + h*64 + ckv*16;
    const unsigned short* vh0 = qh_g + (rowbase + rkv) * QKV_W + 2*E_DIM + h*64 + ckv*16;
    const unsigned short* vl0 = ql_g + (rowbase + rkv) * QKV_W + 2*E_DIM + h*64 + ckv*16;

    #define FS_ISSUE(jt) do {                                              \
        if ((jt) < nj) {                                                   \
            uint32_t sg = sb + (uint32_t)((jt) % 3) * FST_STG;             \
            size_t off = (size_t)(jt) * 64 * QKV_W;                        \
            CPA16(sg + skv,                  kh0 + off);                   \
            CPA16(sg + skv + 16,             kh0 + off + 8);               \
            CPA16(sg + FST_TIL + skv,        kl0 + off);                   \
            CPA16(sg + FST_TIL + skv + 16,   kl0 + off + 8);               \
            CPA16(sg + 2*FST_TIL + skv,      vh0 + off);                   \
            CPA16(sg + 2*FST_TIL + skv + 16, vh0 + off + 8);               \
            CPA16(sg + 3*FST_TIL + skv,      vl0 + off);                   \
            CPA16(sg + 3*FST_TIL + skv + 16, vl0 + off + 8);               \
        }                                                                  \
        CPC();                                                             \
    } while (0)

    FS_ISSUE(0);
    FS_ISSUE(1);

    for (int jt = 0; jt < nj; jt++) {
        CPW(1);
        __syncthreads();
        FS_ISSUE(jt + 2);

        if (jt*64 > rowlim) continue;

        uint32_t Khi = sb + (uint32_t)(jt % 3) * FST_STG;
        uint32_t Klo = Khi + FST_TIL;
        uint32_t Vhi = Khi + 2*FST_TIL;
        uint32_t Vlo = Khi + 3*FST_TIL;

        float s[8][4];
        #pragma unroll
        for (int nt = 0; nt < 8; nt++)
            #pragma unroll
            for (int i = 0; i < 4; i++) s[nt][i] = 0.f;
        {
            uint32_t kb[16];
            #pragma unroll
            for (int ks = 0; ks < 4; ks++) {
                #pragma unroll
                for (int i = 0; i < 4; i++)
                    ldsm4(kb + 4*i, Khi + rpB + (uint32_t)i*2304 + ks*32);
                #pragma unroll
                for (int nt = 0; nt < 8; nt++)
                    mma16816(s[nt], qh[ks], kb + 2*nt);
                #pragma unroll
                for (int nt = 0; nt < 8; nt++)
                    mma16816(s[nt], ql[ks], kb + 2*nt);
                #pragma unroll
                for (int i = 0; i < 4; i++)
                    ldsm4(kb + 4*i, Klo + rpB + (uint32_t)i*2304 + ks*32);
                #pragma unroll
                for (int nt = 0; nt < 8; nt++)
                    mma16816(s[nt], qh[ks], kb + 2*nt);
            }
        }
        #pragma unroll
        for (int nt = 0; nt < 8; nt++)
            #pragma unroll
            for (int i = 0; i < 4; i++) s[nt][i] *= 0.125f;

        int row0 = qi*128 + wid*16 + (lane >> 2);
        if (jt >= 2*qi) {
            #pragma unroll
            for (int nt = 0; nt < 8; nt++) {
                int col = jt*64 + nt*8 + (lane & 3)*2;
                if (col     > row0)     s[nt][0] = -1e30f;
                if (col + 1 > row0)     s[nt][1] = -1e30f;
                if (col     > row0 + 8) s[nt][2] = -1e30f;
                if (col + 1 > row0 + 8) s[nt][3] = -1e30f;
            }
        }

        float m0 = -1e30f, m1 = -1e30f;
        #pragma unroll
        for (int nt = 0; nt < 8; nt++) {
            m0 = fmaxf(m0, fmaxf(s[nt][0], s[nt][1]));
            m1 = fmaxf(m1, fmaxf(s[nt][2], s[nt][3]));
        }
        m0 = fmaxf(m0, __shfl_xor_sync(0xffffffffu, m0, 1));
        m0 = fmaxf(m0, __shfl_xor_sync(0xffffffffu, m0, 2));
        m1 = fmaxf(m1, __shfl_xor_sync(0xffffffffu, m1, 1));
        m1 = fmaxf(m1, __shfl_xor_sync(0xffffffffu, m1, 2));

        float mn0 = fmaxf(rm0, m0), mn1 = fmaxf(rm1, m1);
        float al0 = __expf(rm0 - mn0), al1 = __expf(rm1 - mn1);
        rm0 = mn0; rm1 = mn1;

        float sum0 = 0.f, sum1 = 0.f;
        #pragma unroll
        for (int nt = 0; nt < 8; nt++) {
            s[nt][0] = __expf(s[nt][0] - mn0);
            s[nt][1] = __expf(s[nt][1] - mn0);
            s[nt][2] = __expf(s[nt][2] - mn1);
            s[nt][3] = __expf(s[nt][3] - mn1);
            sum0 += s[nt][0] + s[nt][1];
            sum1 += s[nt][2] + s[nt][3];
        }
        sum0 += __shfl_xor_sync(0xffffffffu, sum0, 1);
        sum0 += __shfl_xor_sync(0xffffffffu, sum0, 2);
        sum1 += __shfl_xor_sync(0xffffffffu, sum1, 1);
        sum1 += __shfl_xor_sync(0xffffffffu, sum1, 2);
        rl0 = rl0 * al0 + sum0;
        rl1 = rl1 * al1 + sum1;

        #pragma unroll
        for (int nt = 0; nt < 8; nt++) {
            oacc[nt][0] *= al0; oacc[nt][1] *= al0;
            oacc[nt][2] *= al1; oacc[nt][3] *= al1;
        }

        uint32_t ph[4][4], pl[4][4];
        #pragma unroll
        for (int ks = 0; ks < 4; ks++) {
            int j0 = 2*ks, j1 = 2*ks + 1;
            packhl(s[j0][0], s[j0][1], ph[ks][0], pl[ks][0]);
            packhl(s[j0][2], s[j0][3], ph[ks][1], pl[ks][1]);
            packhl(s[j1][0], s[j1][1], ph[ks][2], pl[ks][2]);
            packhl(s[j1][2], s[j1][3], ph[ks][3], pl[ks][3]);
        }

        {
            uint32_t vb[16];
            #pragma unroll
            for (int ks = 0; ks < 4; ks++) {
                #pragma unroll
                for (int i = 0; i < 4; i++)
                    ldsm4t(vb + 4*i, Vhi + rpV + (uint32_t)ks*2304 + (uint32_t)i*32);
                #pragma unroll
                for (int nt = 0; nt < 8; nt++)
                    mma16816(oacc[nt], ph[ks], vb + 2*nt);
                #pragma unroll
                for (int nt = 0; nt < 8; nt++)
                    mma16816(oacc[nt], pl[ks], vb + 2*nt);
                #pragma unroll
                for (int i = 0; i < 4; i++)
                    ldsm4t(vb + 4*i, Vlo + rpV + (uint32_t)ks*2304 + (uint32_t)i*32);
                #pragma unroll
                for (int nt = 0; nt < 8; nt++)
                    mma16816(oacc[nt], ph[ks], vb + 2*nt);
            }
        }
    }
    #undef FS_ISSUE

    float inv0 = 1.0f / rl0, inv1 = 1.0f / rl1;
    int row0 = qi*128 + wid*16 + (lane >> 2);
    size_t obase = (size_t)b * S_DIM * E_DIM + h * 64;
    #pragma unroll
    for (int nt = 0; nt < 8; nt++) {
        int col = nt*8 + (lane & 3)*2;
        uint32_t h0, l0, h1, l1;
        packhl(oacc[nt][0]*inv0, oacc[nt][1]*inv0, h0, l0);
        packhl(oacc[nt][2]*inv1, oacc[nt][3]*inv1, h1, l1);
        *(uint32_t*)(oh + obase + (size_t)row0       * E_DIM + col) = h0;
        *(uint32_t*)(ol + obase + (size_t)row0       * E_DIM + col) = l0;
        *(uint32_t*)(oh + obase + (size_t)(row0 + 8) * E_DIM + col) = h1;
        *(uint32_t*)(ol + obase + (size_t)(row0 + 8) * E_DIM + col) = l1;
    }
}

// ---------------- launch ----------------
extern "C" void kernel_launch(void* const* d_in, const int* in_sizes, int n_in,
                              void* d_out, int out_size)
{
    const float* x      = (const float*)d_in[0];
    const float* w_in   = (const float*)d_in[1];
    const float* w_out  = (const float*)d_in[2];
    const float* w_fc   = (const float*)d_in[3];
    const float* b_fc   = (const float*)d_in[4];
    const float* w_proj = (const float*)d_in[5];
    const float* b_proj = (const float*)d_in[6];
    float* out = (float*)d_out;

    void *px2, *phh, *phl, *pqh, *pql, *poh, *pol, *pmh, *pml;
    void *pwinh, *pwinl, *pwouth, *pwoutl, *pwfch, *pwfcl, *pwprh, *pwprl;
    cudaGetSymbolAddress(&px2,  g_x2);
    cudaGetSymbolAddress(&phh,  g_hh);   cudaGetSymbolAddress(&phl,  g_hl);
    cudaGetSymbolAddress(&pqh,  g_qkvh); cudaGetSymbolAddress(&pql,  g_qkvl);
    cudaGetSymbolAddress(&poh,  g_oh);   cudaGetSymbolAddress(&pol,  g_ol);
    cudaGetSymbolAddress(&pmh,  g_mh);   cudaGetSymbolAddress(&pml,  g_ml);
    cudaGetSymbolAddress(&pwinh,  g_winh);  cudaGetSymbolAddress(&pwinl,  g_winl);
    cudaGetSymbolAddress(&pwouth, g_wouth); cudaGetSymbolAddress(&pwoutl, g_woutl);
    cudaGetSymbolAddress(&pwfch,  g_wfch);  cudaGetSymbolAddress(&pwfcl,  g_wfcl);
    cudaGetSymbolAddress(&pwprh,  g_wprh);  cudaGetSymbolAddress(&pwprl,  g_wprl);

    float* bx2  = (float*)px2;
    unsigned short *bhh = (unsigned short*)phh, *bhl = (unsigned short*)phl;
    unsigned short *bqh = (unsigned short*)pqh, *bql = (unsigned short*)pql;
    unsigned short *boh = (unsigned short*)poh, *bol = (unsigned short*)pol;
    unsigned short *bmh = (unsigned short*)pmh, *bml = (unsigned short*)pml;
    unsigned short *winh = (unsigned short*)pwinh, *winl = (unsigned short*)pwinl;
    unsigned short *wouth = (unsigned short*)pwouth, *woutl = (unsigned short*)pwoutl;
    unsigned short *wfch = (unsigned short*)pwfch, *wfcl = (unsigned short*)pwfcl;
    unsigned short *wprh = (unsigned short*)pwprh, *wprl = (unsigned short*)pwprl;

    cudaFuncSetAttribute(flash_mma_kernel,
                         cudaFuncAttributeMaxDynamicSharedMemorySize, FST_SMEM);
    cudaFuncSetAttribute(gemm_bf16_kernel<F_OUTBF>,
                         cudaFuncAttributeMaxDynamicSharedMemorySize, GB_SMEM);
    cudaFuncSetAttribute(gemm_bf16_kernel<F_RES>,
                         cudaFuncAttributeMaxDynamicSharedMemorySize, GB_SMEM);
    cudaFuncSetAttribute(gemm_bf16_kernel<F_BIAS|F_RELU|F_OUTBF>,
                         cudaFuncAttributeMaxDynamicSharedMemorySize, GB_SMEM);
    cudaFuncSetAttribute(gemm_bf16_kernel<F_BIAS|F_RES>,
                         cudaFuncAttributeMaxDynamicSharedMemorySize, GB_SMEM);

    // 0) weight conversions (single launch)
    cvtw_all_kernel<<<1536, 256>>>(w_in, w_out, w_fc, w_proj,
                                   winh, winl, wouth, woutl,
                                   wfch, wfcl, wprh, wprl);

    // 1) h = LN(x) -> bf16 hi/lo
    ln_kernel<<<NROWS, 256>>>(x, bhh, bhl);
    // 2) qkv = h @ w_in^T -> bf16 hi/lo
    gemm_bf16_kernel<F_OUTBF><<<dim3(3072/128, NROWS/128), 256, GB_SMEM>>>(
        bhh, bhl, winh, winl, nullptr, nullptr, nullptr, bqh, bql,
        NROWS, 3072, 1024);
    // 3) o = causal attention(qkv) -> bf16 hi/lo
    flash_mma_kernel<<<dim3(S_DIM/128, B_DIM*H_DIM), 256, FST_SMEM>>>(
        bqh, bql, boh, bol);
    // 4) x2 = o @ w_out^T + x   (fp32)
    gemm_bf16_kernel<F_RES><<<dim3(1024/128, NROWS/128), 256, GB_SMEM>>>(
        boh, bol, wouth, woutl, nullptr, x, bx2, nullptr, nullptr,
        NROWS, 1024, 1024);
    // 5) h2 = LN(x2) -> bf16 hi/lo
    ln_kernel<<<NROWS, 256>>>(bx2, bhh, bhl);
    // 6) m = relu(h2 @ w_fc^T + b_fc) -> bf16 hi/lo
    gemm_bf16_kernel<F_BIAS|F_RELU|F_OUTBF><<<dim3(4096/128, NROWS/128), 256, GB_SMEM>>>(
        bhh, bhl, wfch, wfcl, b_fc, nullptr, nullptr, bmh, bml,
        NROWS, 4096, 1024);
    // 7) out = m @ w_proj^T + b_proj + x2   (fp32)
    gemm_bf16_kernel<F_BIAS|F_RES><<<dim3(1024/128, NROWS/128), 256, GB_SMEM>>>(
        bmh, bml, wprh, wprl, b_proj, bx2, out, nullptr, nullptr,
        NROWS, 1024, 4096);
}

// round 15
// speedup vs baseline: 1.0113x; 1.0113x over previous
#include <cuda_runtime.h>
#include <cuda_bf16.h>
#include <math.h>
#include <stdint.h>

#define E_DIM 1024
#define S_DIM 2048
#define B_DIM 2
#define H_DIM 16
#define NROWS (B_DIM * S_DIM)   // 4096

// ---------------- scratch (no allocations allowed) ----------------
__device__ float g_x2 [(size_t)NROWS * E_DIM];
// bf16 hi/lo activation buffers
__device__ __align__(16) unsigned short g_hh[(size_t)NROWS * E_DIM];
__device__ __align__(16) unsigned short g_hl[(size_t)NROWS * E_DIM];
__device__ __align__(16) unsigned short g_qkvh[(size_t)NROWS * 3 * E_DIM];
__device__ __align__(16) unsigned short g_qkvl[(size_t)NROWS * 3 * E_DIM];
__device__ __align__(16) unsigned short g_oh[(size_t)NROWS * E_DIM];
__device__ __align__(16) unsigned short g_ol[(size_t)NROWS * E_DIM];
__device__ __align__(16) unsigned short g_mh[(size_t)NROWS * 4 * E_DIM];
__device__ __align__(16) unsigned short g_ml[(size_t)NROWS * 4 * E_DIM];
// bf16 hi/lo weights
__device__ __align__(16) unsigned short g_winh [(size_t)3*E_DIM*E_DIM];
__device__ __align__(16) unsigned short g_winl [(size_t)3*E_DIM*E_DIM];
__device__ __align__(16) unsigned short g_wouth[(size_t)E_DIM*E_DIM];
__device__ __align__(16) unsigned short g_woutl[(size_t)E_DIM*E_DIM];
__device__ __align__(16) unsigned short g_wfch [(size_t)4*E_DIM*E_DIM];
__device__ __align__(16) unsigned short g_wfcl [(size_t)4*E_DIM*E_DIM];
__device__ __align__(16) unsigned short g_wprh [(size_t)4*E_DIM*E_DIM];
__device__ __align__(16) unsigned short g_wprl [(size_t)4*E_DIM*E_DIM];

// ================= helpers =================
__device__ __forceinline__ uint32_t smem_u32(const void* p) {
    uint32_t a;
    asm("{ .reg .u64 t; cvta.to.shared.u64 t, %1; cvt.u32.u64 %0, t; }"
        : "=r"(a) : "l"(p));
    return a;
}

__device__ __forceinline__ void ldsm4(uint32_t* r, uint32_t addr) {
    asm volatile("ldmatrix.sync.aligned.m8n8.x4.shared.b16 {%0,%1,%2,%3}, [%4];"
        : "=r"(r[0]), "=r"(r[1]), "=r"(r[2]), "=r"(r[3]) : "r"(addr));
}

__device__ __forceinline__ void ldsm4t(uint32_t* r, uint32_t addr) {
    asm volatile("ldmatrix.sync.aligned.m8n8.x4.trans.shared.b16 {%0,%1,%2,%3}, [%4];"
        : "=r"(r[0]), "=r"(r[1]), "=r"(r[2]), "=r"(r[3]) : "r"(addr));
}

__device__ __forceinline__ void mma16816(float* d, const uint32_t* a, const uint32_t* b) {
    asm volatile(
        "mma.sync.aligned.m16n8k16.row.col.f32.bf16.bf16.f32 "
        "{%0,%1,%2,%3}, {%4,%5,%6,%7}, {%8,%9}, {%0,%1,%2,%3};"
        : "+f"(d[0]), "+f"(d[1]), "+f"(d[2]), "+f"(d[3])
        : "r"(a[0]), "r"(a[1]), "r"(a[2]), "r"(a[3]), "r"(b[0]), "r"(b[1]));
}

#define CPA16(dst, src) \
    asm volatile("cp.async.cg.shared.global [%0], [%1], 16;" \
        :: "r"(dst), "l"(src) : "memory")
#define CPC() asm volatile("cp.async.commit_group;" ::: "memory")
#define CPW(n) asm volatile("cp.async.wait_group %0;" :: "n"(n) : "memory")

__device__ __forceinline__ void cvt8(float4 v0, float4 v1, uint4& hi, uint4& lo) {
    float x[8] = {v0.x, v0.y, v0.z, v0.w, v1.x, v1.y, v1.z, v1.w};
    uint32_t h[4], l[4];
    #pragma unroll
    for (int i = 0; i < 4; i++) {
        __nv_bfloat16 a = __float2bfloat16_rn(x[2*i]);
        __nv_bfloat16 b = __float2bfloat16_rn(x[2*i+1]);
        __nv_bfloat16 c = __float2bfloat16_rn(x[2*i]   - __bfloat162float(a));
        __nv_bfloat16 d = __float2bfloat16_rn(x[2*i+1] - __bfloat162float(b));
        h[i] = (uint32_t)__bfloat16_as_ushort(a) | ((uint32_t)__bfloat16_as_ushort(b) << 16);
        l[i] = (uint32_t)__bfloat16_as_ushort(c) | ((uint32_t)__bfloat16_as_ushort(d) << 16);
    }
    hi = make_uint4(h[0], h[1], h[2], h[3]);
    lo = make_uint4(l[0], l[1], l[2], l[3]);
}

__device__ __forceinline__ void packhl(float a, float b, uint32_t& hi, uint32_t& lo) {
    __nv_bfloat16 ah = __float2bfloat16_rn(a);
    __nv_bfloat16 bh = __float2bfloat16_rn(b);
    __nv_bfloat16 al = __float2bfloat16_rn(a - __bfloat162float(ah));
    __nv_bfloat16 bl = __float2bfloat16_rn(b - __bfloat162float(bh));
    hi = (uint32_t)__bfloat16_as_ushort(ah) | ((uint32_t)__bfloat16_as_ushort(bh) << 16);
    lo = (uint32_t)__bfloat16_as_ushort(al) | ((uint32_t)__bfloat16_as_ushort(bl) << 16);
}

// ---------------- merged weight fp32 -> bf16 hi/lo (one launch) ----------------
#define CW_N0 393216
#define CW_N1 (CW_N0 + 131072)
#define CW_N2 (CW_N1 + 524288)
#define CW_N3 (CW_N2 + 524288)

__global__ __launch_bounds__(256) void cvtw_all_kernel(
    const float* __restrict__ s0, const float* __restrict__ s1,
    const float* __restrict__ s2, const float* __restrict__ s3,
    unsigned short* __restrict__ h0, unsigned short* __restrict__ l0,
    unsigned short* __restrict__ h1, unsigned short* __restrict__ l1,
    unsigned short* __restrict__ h2, unsigned short* __restrict__ l2,
    unsigned short* __restrict__ h3, unsigned short* __restrict__ l3)
{
    for (int i = blockIdx.x * blockDim.x + threadIdx.x; i < CW_N3;
         i += gridDim.x * blockDim.x) {
        const float* src; unsigned short *dh, *dl; int j;
        if (i < CW_N0)      { src = s0; dh = h0; dl = l0; j = i; }
        else if (i < CW_N1) { src = s1; dh = h1; dl = l1; j = i - CW_N0; }
        else if (i < CW_N2) { src = s2; dh = h2; dl = l2; j = i - CW_N1; }
        else                { src = s3; dh = h3; dl = l3; j = i - CW_N2; }
        float4 v0 = *(const float4*)(src + (size_t)j * 8);
        float4 v1 = *(const float4*)(src + (size_t)j * 8 + 4);
        uint4 h, l;
        cvt8(v0, v1, h, l);
        ((uint4*)dh)[j] = h;
        ((uint4*)dl)[j] = l;
    }
}

// ---------------- LayerNorm -> bf16 hi/lo ----------------
__global__ __launch_bounds__(256) void ln_kernel(const float* __restrict__ x,
                                                 unsigned short* __restrict__ yh,
                                                 unsigned short* __restrict__ yl)
{
    int row = blockIdx.x;
    int tid = threadIdx.x;
    const float* xr = x + (size_t)row * E_DIM;

    float4 v = *(const float4*)(xr + tid * 4);
    float s  = v.x + v.y + v.z + v.w;
    float ss = v.x*v.x + v.y*v.y + v.z*v.z + v.w*v.w;

    #pragma unroll
    for (int off = 16; off > 0; off >>= 1) {
        s  += __shfl_xor_sync(0xffffffffu, s,  off);
        ss += __shfl_xor_sync(0xffffffffu, ss, off);
    }

    __shared__ float rs[8], rss[8], stat[2];
    int wid = tid >> 5, lane = tid & 31;
    if (lane == 0) { rs[wid] = s; rss[wid] = ss; }
    __syncthreads();
    if (tid == 0) {
        float t = 0.f, tt = 0.f;
        #pragma unroll
        for (int i = 0; i < 8; i++) { t += rs[i]; tt += rss[i]; }
        float mean = t * (1.0f / E_DIM);
        float var  = tt * (1.0f / E_DIM) - mean * mean;
        stat[0] = mean;
        stat[1] = rsqrtf(var + 1e-5f);
    }
    __syncthreads();
    float mean = stat[0], rstd = stat[1];
    float o0 = (v.x - mean) * rstd, o1 = (v.y - mean) * rstd;
    float o2 = (v.z - mean) * rstd, o3 = (v.w - mean) * rstd;
    uint32_t h0, l0, h1, l1;
    packhl(o0, o1, h0, l0);
    packhl(o2, o3, h1, l1);
    uint2 hh = make_uint2(h0, h1), ll = make_uint2(l0, l1);
    *(uint2*)(yh + (size_t)row * E_DIM + tid * 4) = hh;
    *(uint2*)(yl + (size_t)row * E_DIM + tid * 4) = ll;
}

// ================= bf16x3 GEMM: BK=16, 4-stage cp.async, 1 sync/stage =================
#define F_BIAS  1
#define F_RELU  2
#define F_RES   4
#define F_OUTBF 8

#define GB_TILE  6144               // 128 rows x 48 B (32 B data + 16 pad)
#define GB_STAGE (4 * GB_TILE)      // 24576
#define GB_SMEM  (4 * GB_STAGE)     // 98304; x2 CTAs = 196608 <= 228KB

template<int FLAGS>
__global__ __launch_bounds__(256, 2)
void gemm_bf16_kernel(const unsigned short* __restrict__ Ah,
                      const unsigned short* __restrict__ Al,
                      const unsigned short* __restrict__ Bh,
                      const unsigned short* __restrict__ Bl,
                      const float* __restrict__ bias, const float* __restrict__ res,
                      float* __restrict__ C,
                      unsigned short* __restrict__ Ch, unsigned short* __restrict__ Cl,
                      int M, int N, int K)
{
    extern __shared__ __align__(16) char smem[];
    uint32_t sb = smem_u32(smem);

    int tid = threadIdx.x;
    int lane = tid & 31, wid = tid >> 5;
    int wm = wid >> 1, wn = wid & 1;
    int bn = blockIdx.x, bm = blockIdx.y;

    // cp.async mapping: row = tid>>1 (0..127), 16B half c0
    int r0 = tid >> 1, c0 = tid & 1;
    uint32_t so = (uint32_t)(r0 * 48 + c0 * 16);
    size_t goff = (size_t)r0 * K + c0 * 8;
    const unsigned short* pA0 = Ah + (size_t)(bm * 128) * K + goff;
    const unsigned short* pL0 = Al + (size_t)(bm * 128) * K + goff;
    const unsigned short* pB0 = Bh + (size_t)(bn * 128) * K + goff;
    const unsigned short* pX0 = Bl + (size_t)(bn * 128) * K + goff;

    uint32_t rpA = (uint32_t)((wm * 32 + (lane & 15)) * 48 + (lane >> 4) * 16);
    int g = lane >> 3, l8 = lane & 7;
    uint32_t rpB = (uint32_t)((wn * 64 + l8 + (g >> 1) * 8) * 48 + (g & 1) * 16);

    float acc[2][8][4];
    #pragma unroll
    for (int mt = 0; mt < 2; mt++)
        #pragma unroll
        for (int nt = 0; nt < 8; nt++)
            #pragma unroll
            for (int i = 0; i < 4; i++) acc[mt][nt][i] = 0.f;

    int nch = K >> 4;

    #define GB_ISSUE(kc) do {                                            \
        if ((kc) < nch) {                                                \
            uint32_t sa = sb + (uint32_t)((kc) & 3) * GB_STAGE;          \
            int off = (kc) * 16;                                         \
            CPA16(sa + so,               pA0 + off);                     \
            CPA16(sa + GB_TILE + so,     pL0 + off);                     \
            CPA16(sa + 2*GB_TILE + so,   pB0 + off);                     \
            CPA16(sa + 3*GB_TILE + so,   pX0 + off);                     \
        }                                                                \
        CPC();                                                           \
    } while (0)

    GB_ISSUE(0);
    GB_ISSUE(1);
    GB_ISSUE(2);

    for (int kc = 0; kc < nch; kc++) {
        CPW(2);               // stage kc landed; 2 stages of slack in flight
        __syncthreads();

        uint32_t base = sb + (uint32_t)(kc & 3) * GB_STAGE;
        uint32_t aHi = base, aLo = base + GB_TILE;
        uint32_t bHi = base + 2*GB_TILE, bLo = base + 3*GB_TILE;

        uint32_t ah[8], ax[8], bb[16];
        ldsm4(ah + 0, aHi + rpA);
        ldsm4(ah + 4, aHi + rpA + 768);     // +16 rows (16*48) — FIXED
        ldsm4(ax + 0, aLo + rpA);
        ldsm4(ax + 4, aLo + rpA + 768);     // FIXED
        #pragma unroll
        for (int i = 0; i < 4; i++)
            ldsm4(bb + i*4, bHi + rpB + (uint32_t)i*768);
        #pragma unroll
        for (int mt = 0; mt < 2; mt++)
            #pragma unroll
            for (int nt = 0; nt < 8; nt++)
                mma16816(acc[mt][nt], ah + mt*4, bb + nt*2);
        #pragma unroll
        for (int mt = 0; mt < 2; mt++)
            #pragma unroll
            for (int nt = 0; nt < 8; nt++)
                mma16816(acc[mt][nt], ax + mt*4, bb + nt*2);
        #pragma unroll
        for (int i = 0; i < 4; i++)
            ldsm4(bb + i*4, bLo + rpB + (uint32_t)i*768);
        #pragma unroll
        for (int mt = 0; mt < 2; mt++)
            #pragma unroll
            for (int nt = 0; nt < 8; nt++)
                mma16816(acc[mt][nt], ah + mt*4, bb + nt*2);

        GB_ISSUE(kc + 3);
    }
    #undef GB_ISSUE

    // ---- epilogue ----
    #pragma unroll
    for (int mt = 0; mt < 2; mt++) {
        int gr0 = bm*128 + wm*32 + mt*16 + (lane >> 2);
        #pragma unroll
        for (int nt = 0; nt < 8; nt++) {
            int gc = bn*128 + wn*64 + nt*8 + (lane & 3)*2;
            #pragma unroll
            for (int hfl = 0; hfl < 2; hfl++) {
                int row = gr0 + hfl*8;
                float v0 = acc[mt][nt][hfl*2+0];
                float v1 = acc[mt][nt][hfl*2+1];
                if (FLAGS & F_BIAS) {
                    v0 += __ldg(bias + gc);
                    v1 += __ldg(bias + gc + 1);
                }
                if (FLAGS & F_RES) {
                    float2 rr = *(const float2*)(res + (size_t)row * N + gc);
                    v0 += rr.x; v1 += rr.y;
                }
                if (FLAGS & F_RELU) { v0 = fmaxf(v0, 0.f); v1 = fmaxf(v1, 0.f); }
                if (FLAGS & F_OUTBF) {
                    uint32_t h, l;
                    packhl(v0, v1, h, l);
                    *(uint32_t*)(Ch + (size_t)row * N + gc) = h;
                    *(uint32_t*)(Cl + (size_t)row * N + gc) = l;
                } else {
                    float2 o = make_float2(v0, v1);
                    *(float2*)(C + (size_t)row * N + gc) = o;
                }
            }
        }
    }
}

// ================= Flash attention: bf16 hi/lo in, cp.async 3-stage, occ 2 =================
#define FST_TIL  9216                 // 64*144
#define FST_STG  (4 * FST_TIL)        // 36864
#define FST_SMEM (3 * FST_STG)        // 110592; x2 CTAs = 221184 <= 228KB

__global__ __launch_bounds__(256, 2)
void flash_mma_kernel(const unsigned short* __restrict__ qh_g,
                      const unsigned short* __restrict__ ql_g,
                      unsigned short* __restrict__ oh,
                      unsigned short* __restrict__ ol)
{
    extern __shared__ __align__(16) char smf[];
    uint32_t sb  = smem_u32(smf);

    int tid = threadIdx.x, lane = tid & 31, wid = tid >> 5;
    int qi = (int)gridDim.x - 1 - (int)blockIdx.x;   // longest CTAs first
    int bh = blockIdx.y;
    int b = bh >> 4, h = bh & 15;

    const int QKV_W = 3 * E_DIM;   // 3072
    size_t rowbase = (size_t)b * S_DIM;

    // ---- stage Q (hi/lo) through stage-0/1 smem, build register fragments ----
    {
        int r = tid >> 1, ce = (tid & 1) * 32;
        const unsigned short* sh = qh_g + (rowbase + qi*128 + r) * QKV_W + h*64 + ce;
        const unsigned short* sl = ql_g + (rowbase + qi*128 + r) * QKV_W + h*64 + ce;
        uint32_t d = sb + (uint32_t)(r*144 + ce*2);
        #pragma unroll
        for (int k = 0; k < 4; k++) {
            CPA16(d + k*16,         sh + k*8);
            CPA16(d + 18432 + k*16, sl + k*8);
        }
        CPC(); CPW(0);
    }
    __syncthreads();

    uint32_t qh[4][4], ql[4][4];
    {
        uint32_t ra = sb + (uint32_t)((wid*16 + (lane & 15))*144 + (lane >> 4)*16);
        #pragma unroll
        for (int ks = 0; ks < 4; ks++) {
            ldsm4(qh[ks], ra + ks*32);
            ldsm4(ql[ks], ra + 18432 + ks*32);
        }
    }
    __syncthreads();

    float oacc[8][4];
    #pragma unroll
    for (int nt = 0; nt < 8; nt++)
        #pragma unroll
        for (int i = 0; i < 4; i++) oacc[nt][i] = 0.f;
    float rm0 = -1e30f, rm1 = -1e30f, rl0 = 0.f, rl1 = 0.f;

    int g = lane >> 3, l8 = lane & 7;
    uint32_t rpB = (uint32_t)((l8 + (g >> 1)*8)*144 + (g & 1)*16);
    uint32_t rpV = (uint32_t)((lane & 15)*144 + (lane >> 4)*16);

    int rowlim = qi*128 + wid*16 + 15;
    int nj = 2*qi + 2;

    int rkv = tid >> 2, ckv = tid & 3;
    uint32_t skv = (uint32_t)(rkv*144 + ckv*32);
    const unsigned short* kh0 = qh_g + (rowbase + rkv) * QKV_W + E_DIM   + h*64 + ckv*16;
    const unsigned short* kl0 = ql_g + (rowbase + rkv) * QKV_W + E_DIM   + h*64 + ckv*16;
    const unsigned short* vh0 = qh_g + (rowbase + rkv) * QKV_W + 2*E_DIM + h*64 + ckv*16;
    const unsigned short* vl0 = ql_g + (rowbase + rkv) * QKV_W + 2*E_DIM + h*64 + ckv*16;

    #define FS_ISSUE(jt) do {                                              \
        if ((jt) < nj) {                                                   \
            uint32_t sg = sb + (uint32_t)((jt) % 3) * FST_STG;             \
            size_t off = (size_t)(jt) * 64 * QKV_W;                        \
            CPA16(sg + skv,                  kh0 + off);                   \
            CPA16(sg + skv + 16,             kh0 + off + 8);               \
            CPA16(sg + FST_TIL + skv,        kl0 + off);                   \
            CPA16(sg + FST_TIL + skv + 16,   kl0 + off + 8);               \
            CPA16(sg + 2*FST_TIL + skv,      vh0 + off);                   \
            CPA16(sg + 2*FST_TIL + skv + 16, vh0 + off + 8);               \
            CPA16(sg + 3*FST_TIL + skv,      vl0 + off);                   \
            CPA16(sg + 3*FST_TIL + skv + 16, vl0 + off + 8);               \
        }                                                                  \
        CPC();                                                             \
    } while (0)

    FS_ISSUE(0);
    FS_ISSUE(1);

    for (int jt = 0; jt < nj; jt++) {
        CPW(1);
        __syncthreads();
        FS_ISSUE(jt + 2);

        if (jt*64 > rowlim) continue;

        uint32_t Khi = sb + (uint32_t)(jt % 3) * FST_STG;
        uint32_t Klo = Khi + FST_TIL;
        uint32_t Vhi = Khi + 2*FST_TIL;
        uint32_t Vlo = Khi + 3*FST_TIL;

        float s[8][4];
        #pragma unroll
        for (int nt = 0; nt < 8; nt++)
            #pragma unroll
            for (int i = 0; i < 4; i++) s[nt][i] = 0.f;
        {
            uint32_t kb[16];
            #pragma unroll
            for (int ks = 0; ks < 4; ks++) {
                #pragma unroll
                for (int i = 0; i < 4; i++)
                    ldsm4(kb + 4*i, Khi + rpB + (uint32_t)i*2304 + ks*32);
                #pragma unroll
                for (int nt = 0; nt < 8; nt++)
                    mma16816(s[nt], qh[ks], kb + 2*nt);
                #pragma unroll
                for (int nt = 0; nt < 8; nt++)
                    mma16816(s[nt], ql[ks], kb + 2*nt);
                #pragma unroll
                for (int i = 0; i < 4; i++)
                    ldsm4(kb + 4*i, Klo + rpB + (uint32_t)i*2304 + ks*32);
                #pragma unroll
                for (int nt = 0; nt < 8; nt++)
                    mma16816(s[nt], qh[ks], kb + 2*nt);
            }
        }
        #pragma unroll
        for (int nt = 0; nt < 8; nt++)
            #pragma unroll
            for (int i = 0; i < 4; i++) s[nt][i] *= 0.125f;

        int row0 = qi*128 + wid*16 + (lane >> 2);
        if (jt >= 2*qi) {
            #pragma unroll
            for (int nt = 0; nt < 8; nt++) {
                int col = jt*64 + nt*8 + (lane & 3)*2;
                if (col     > row0)     s[nt][0] = -1e30f;
                if (col + 1 > row0)     s[nt][1] = -1e30f;
                if (col     > row0 + 8) s[nt][2] = -1e30f;
                if (col + 1 > row0 + 8) s[nt][3] = -1e30f;
            }
        }

        float m0 = -1e30f, m1 = -1e30f;
        #pragma unroll
        for (int nt = 0; nt < 8; nt++) {
            m0 = fmaxf(m0, fmaxf(s[nt][0], s[nt][1]));
            m1 = fmaxf(m1, fmaxf(s[nt][2], s[nt][3]));
        }
        m0 = fmaxf(m0, __shfl_xor_sync(0xffffffffu, m0, 1));
        m0 = fmaxf(m0, __shfl_xor_sync(0xffffffffu, m0, 2));
        m1 = fmaxf(m1, __shfl_xor_sync(0xffffffffu, m1, 1));
        m1 = fmaxf(m1, __shfl_xor_sync(0xffffffffu, m1, 2));

        float mn0 = fmaxf(rm0, m0), mn1 = fmaxf(rm1, m1);
        float al0 = __expf(rm0 - mn0), al1 = __expf(rm1 - mn1);
        rm0 = mn0; rm1 = mn1;

        float sum0 = 0.f, sum1 = 0.f;
        #pragma unroll
        for (int nt = 0; nt < 8; nt++) {
            s[nt][0] = __expf(s[nt][0] - mn0);
            s[nt][1] = __expf(s[nt][1] - mn0);
            s[nt][2] = __expf(s[nt][2] - mn1);
            s[nt][3] = __expf(s[nt][3] - mn1);
            sum0 += s[nt][0] + s[nt][1];
            sum1 += s[nt][2] + s[nt][3];
        }
        sum0 += __shfl_xor_sync(0xffffffffu, sum0, 1);
        sum0 += __shfl_xor_sync(0xffffffffu, sum0, 2);
        sum1 += __shfl_xor_sync(0xffffffffu, sum1, 1);
        sum1 += __shfl_xor_sync(0xffffffffu, sum1, 2);
        rl0 = rl0 * al0 + sum0;
        rl1 = rl1 * al1 + sum1;

        #pragma unroll
        for (int nt = 0; nt < 8; nt++) {
            oacc[nt][0] *= al0; oacc[nt][1] *= al0;
            oacc[nt][2] *= al1; oacc[nt][3] *= al1;
        }

        uint32_t ph[4][4], pl[4][4];
        #pragma unroll
        for (int ks = 0; ks < 4; ks++) {
            int j0 = 2*ks, j1 = 2*ks + 1;
            packhl(s[j0][0], s[j0][1], ph[ks][0], pl[ks][0]);
            packhl(s[j0][2], s[j0][3], ph[ks][1], pl[ks][1]);
            packhl(s[j1][0], s[j1][1], ph[ks][2], pl[ks][2]);
            packhl(s[j1][2], s[j1][3], ph[ks][3], pl[ks][3]);
        }

        {
            uint32_t vb[16];
            #pragma unroll
            for (int ks = 0; ks < 4; ks++) {
                #pragma unroll
                for (int i = 0; i < 4; i++)
                    ldsm4t(vb + 4*i, Vhi + rpV + (uint32_t)ks*2304 + (uint32_t)i*32);
                #pragma unroll
                for (int nt = 0; nt < 8; nt++)
                    mma16816(oacc[nt], ph[ks], vb + 2*nt);
                #pragma unroll
                for (int nt = 0; nt < 8; nt++)
                    mma16816(oacc[nt], pl[ks], vb + 2*nt);
                #pragma unroll
                for (int i = 0; i < 4; i++)
                    ldsm4t(vb + 4*i, Vlo + rpV + (uint32_t)ks*2304 + (uint32_t)i*32);
                #pragma unroll
                for (int nt = 0; nt < 8; nt++)
                    mma16816(oacc[nt], ph[ks], vb + 2*nt);
            }
        }
    }
    #undef FS_ISSUE

    float inv0 = 1.0f / rl0, inv1 = 1.0f / rl1;
    int row0 = qi*128 + wid*16 + (lane >> 2);
    size_t obase = (size_t)b * S_DIM * E_DIM + h * 64;
    #pragma unroll
    for (int nt = 0; nt < 8; nt++) {
        int col = nt*8 + (lane & 3)*2;
        uint32_t h0, l0, h1, l1;
        packhl(oacc[nt][0]*inv0, oacc[nt][1]*inv0, h0, l0);
        packhl(oacc[nt][2]*inv1, oacc[nt][3]*inv1, h1, l1);
        *(uint32_t*)(oh + obase + (size_t)row0       * E_DIM + col) = h0;
        *(uint32_t*)(ol + obase + (size_t)row0       * E_DIM + col) = l0;
        *(uint32_t*)(oh + obase + (size_t)(row0 + 8) * E_DIM + col) = h1;
        *(uint32_t*)(ol + obase + (size_t)(row0 + 8) * E_DIM + col) = l1;
    }
}

// ---------------- launch ----------------
extern "C" void kernel_launch(void* const* d_in, const int* in_sizes, int n_in,
                              void* d_out, int out_size)
{
    const float* x      = (const float*)d_in[0];
    const float* w_in   = (const float*)d_in[1];
    const float* w_out  = (const float*)d_in[2];
    const float* w_fc   = (const float*)d_in[3];
    const float* b_fc   = (const float*)d_in[4];
    const float* w_proj = (const float*)d_in[5];
    const float* b_proj = (const float*)d_in[6];
    float* out = (float*)d_out;

    void *px2, *phh, *phl, *pqh, *pql, *poh, *pol, *pmh, *pml;
    void *pwinh, *pwinl, *pwouth, *pwoutl, *pwfch, *pwfcl, *pwprh, *pwprl;
    cudaGetSymbolAddress(&px2,  g_x2);
    cudaGetSymbolAddress(&phh,  g_hh);   cudaGetSymbolAddress(&phl,  g_hl);
    cudaGetSymbolAddress(&pqh,  g_qkvh); cudaGetSymbolAddress(&pql,  g_qkvl);
    cudaGetSymbolAddress(&poh,  g_oh);   cudaGetSymbolAddress(&pol,  g_ol);
    cudaGetSymbolAddress(&pmh,  g_mh);   cudaGetSymbolAddress(&pml,  g_ml);
    cudaGetSymbolAddress(&pwinh,  g_winh);  cudaGetSymbolAddress(&pwinl,  g_winl);
    cudaGetSymbolAddress(&pwouth, g_wouth); cudaGetSymbolAddress(&pwoutl, g_woutl);
    cudaGetSymbolAddress(&pwfch,  g_wfch);  cudaGetSymbolAddress(&pwfcl,  g_wfcl);
    cudaGetSymbolAddress(&pwprh,  g_wprh);  cudaGetSymbolAddress(&pwprl,  g_wprl);

    float* bx2  = (float*)px2;
    unsigned short *bhh = (unsigned short*)phh, *bhl = (unsigned short*)phl;
    unsigned short *bqh = (unsigned short*)pqh, *bql = (unsigned short*)pql;
    unsigned short *boh = (unsigned short*)poh, *bol = (unsigned short*)pol;
    unsigned short *bmh = (unsigned short*)pmh, *bml = (unsigned short*)pml;
    unsigned short *winh = (unsigned short*)pwinh, *winl = (unsigned short*)pwinl;
    unsigned short *wouth = (unsigned short*)pwouth, *woutl = (unsigned short*)pwoutl;
    unsigned short *wfch = (unsigned short*)pwfch, *wfcl = (unsigned short*)pwfcl;
    unsigned short *wprh = (unsigned short*)pwprh, *wprl = (unsigned short*)pwprl;

    cudaFuncSetAttribute(flash_mma_kernel,
                         cudaFuncAttributeMaxDynamicSharedMemorySize, FST_SMEM);
    cudaFuncSetAttribute(gemm_bf16_kernel<F_OUTBF>,
                         cudaFuncAttributeMaxDynamicSharedMemorySize, GB_SMEM);
    cudaFuncSetAttribute(gemm_bf16_kernel<F_RES>,
                         cudaFuncAttributeMaxDynamicSharedMemorySize, GB_SMEM);
    cudaFuncSetAttribute(gemm_bf16_kernel<F_BIAS|F_RELU|F_OUTBF>,
                         cudaFuncAttributeMaxDynamicSharedMemorySize, GB_SMEM);
    cudaFuncSetAttribute(gemm_bf16_kernel<F_BIAS|F_RES>,
                         cudaFuncAttributeMaxDynamicSharedMemorySize, GB_SMEM);

    // 0) weight conversions (single launch)
    cvtw_all_kernel<<<1536, 256>>>(w_in, w_out, w_fc, w_proj,
                                   winh, winl, wouth, woutl,
                                   wfch, wfcl, wprh, wprl);

    // 1) h = LN(x) -> bf16 hi/lo
    ln_kernel<<<NROWS, 256>>>(x, bhh, bhl);
    // 2) qkv = h @ w_in^T -> bf16 hi/lo
    gemm_bf16_kernel<F_OUTBF><<<dim3(3072/128, NROWS/128), 256, GB_SMEM>>>(
        bhh, bhl, winh, winl, nullptr, nullptr, nullptr, bqh, bql,
        NROWS, 3072, 1024);
    // 3) o = causal attention(qkv) -> bf16 hi/lo
    flash_mma_kernel<<<dim3(S_DIM/128, B_DIM*H_DIM), 256, FST_SMEM>>>(
        bqh, bql, boh, bol);
    // 4) x2 = o @ w_out^T + x   (fp32)
    gemm_bf16_kernel<F_RES><<<dim3(1024/128, NROWS/128), 256, GB_SMEM>>>(
        boh, bol, wouth, woutl, nullptr, x, bx2, nullptr, nullptr,
        NROWS, 1024, 1024);
    // 5) h2 = LN(x2) -> bf16 hi/lo
    ln_kernel<<<NROWS, 256>>>(bx2, bhh, bhl);
    // 6) m = relu(h2 @ w_fc^T + b_fc) -> bf16 hi/lo
    gemm_bf16_kernel<F_BIAS|F_RELU|F_OUTBF><<<dim3(4096/128, NROWS/128), 256, GB_SMEM>>>(
        bhh, bhl, wfch, wfcl, b_fc, nullptr, nullptr, bmh, bml,
        NROWS, 4096, 1024);
    // 7) out = m @ w_proj^T + b_proj + x2   (fp32)
    gemm_bf16_kernel<F_BIAS|F_RES><<<dim3(1024/128, NROWS/128), 256, GB_SMEM>>>(
        bmh, bml, wprh, wprl, b_proj, bx2, out, nullptr, nullptr,
        NROWS, 1024, 4096);
}

// round 16
// speedup vs baseline: 1.4366x; 1.4205x over previous
#include <cuda_runtime.h>
#include <cuda_fp16.h>
#include <math.h>
#include <stdint.h>

#define E_DIM 1024
#define S_DIM 2048
#define B_DIM 2
#define H_DIM 16
#define NROWS (B_DIM * S_DIM)   // 4096

// ---------------- scratch (no allocations allowed) ----------------
__device__ float g_x2 [(size_t)NROWS * E_DIM];
// fp16 activation buffers (hi only except qkv which needs hi+lo as B-operand)
__device__ __align__(16) unsigned short g_hh  [(size_t)NROWS * E_DIM];
__device__ __align__(16) unsigned short g_qkvh[(size_t)NROWS * 3 * E_DIM];
__device__ __align__(16) unsigned short g_qkvl[(size_t)NROWS * 3 * E_DIM];
__device__ __align__(16) unsigned short g_oh  [(size_t)NROWS * E_DIM];
__device__ __align__(16) unsigned short g_mh  [(size_t)NROWS * 4 * E_DIM];
// fp16 hi/lo weights
__device__ __align__(16) unsigned short g_winh [(size_t)3*E_DIM*E_DIM];
__device__ __align__(16) unsigned short g_winl [(size_t)3*E_DIM*E_DIM];
__device__ __align__(16) unsigned short g_wouth[(size_t)E_DIM*E_DIM];
__device__ __align__(16) unsigned short g_woutl[(size_t)E_DIM*E_DIM];
__device__ __align__(16) unsigned short g_wfch [(size_t)4*E_DIM*E_DIM];
__device__ __align__(16) unsigned short g_wfcl [(size_t)4*E_DIM*E_DIM];
__device__ __align__(16) unsigned short g_wprh [(size_t)4*E_DIM*E_DIM];
__device__ __align__(16) unsigned short g_wprl [(size_t)4*E_DIM*E_DIM];

// ================= helpers =================
__device__ __forceinline__ uint32_t smem_u32(const void* p) {
    uint32_t a;
    asm("{ .reg .u64 t; cvta.to.shared.u64 t, %1; cvt.u32.u64 %0, t; }"
        : "=r"(a) : "l"(p));
    return a;
}

__device__ __forceinline__ void ldsm4(uint32_t* r, uint32_t addr) {
    asm volatile("ldmatrix.sync.aligned.m8n8.x4.shared.b16 {%0,%1,%2,%3}, [%4];"
        : "=r"(r[0]), "=r"(r[1]), "=r"(r[2]), "=r"(r[3]) : "r"(addr));
}

__device__ __forceinline__ void ldsm4t(uint32_t* r, uint32_t addr) {
    asm volatile("ldmatrix.sync.aligned.m8n8.x4.trans.shared.b16 {%0,%1,%2,%3}, [%4];"
        : "=r"(r[0]), "=r"(r[1]), "=r"(r[2]), "=r"(r[3]) : "r"(addr));
}

__device__ __forceinline__ void mma16816(float* d, const uint32_t* a, const uint32_t* b) {
    asm volatile(
        "mma.sync.aligned.m16n8k16.row.col.f32.f16.f16.f32 "
        "{%0,%1,%2,%3}, {%4,%5,%6,%7}, {%8,%9}, {%0,%1,%2,%3};"
        : "+f"(d[0]), "+f"(d[1]), "+f"(d[2]), "+f"(d[3])
        : "r"(a[0]), "r"(a[1]), "r"(a[2]), "r"(a[3]), "r"(b[0]), "r"(b[1]));
}

#define CPA16(dst, src) \
    asm volatile("cp.async.cg.shared.global [%0], [%1], 16;" \
        :: "r"(dst), "l"(src) : "memory")
#define CPC() asm volatile("cp.async.commit_group;" ::: "memory")
#define CPW(n) asm volatile("cp.async.wait_group %0;" :: "n"(n) : "memory")

// fp16 hi/lo split of 8 floats
__device__ __forceinline__ void cvt8h(float4 v0, float4 v1, uint4& hi, uint4& lo) {
    float x[8] = {v0.x, v0.y, v0.z, v0.w, v1.x, v1.y, v1.z, v1.w};
    uint32_t h[4], l[4];
    #pragma unroll
    for (int i = 0; i < 4; i++) {
        __half a = __float2half_rn(x[2*i]);
        __half b = __float2half_rn(x[2*i+1]);
        __half c = __float2half_rn(x[2*i]   - __half2float(a));
        __half d = __float2half_rn(x[2*i+1] - __half2float(b));
        h[i] = (uint32_t)__half_as_ushort(a) | ((uint32_t)__half_as_ushort(b) << 16);
        l[i] = (uint32_t)__half_as_ushort(c) | ((uint32_t)__half_as_ushort(d) << 16);
    }
    hi = make_uint4(h[0], h[1], h[2], h[3]);
    lo = make_uint4(l[0], l[1], l[2], l[3]);
}

__device__ __forceinline__ void packhl_h(float a, float b, uint32_t& hi, uint32_t& lo) {
    __half ah = __float2half_rn(a);
    __half bh = __float2half_rn(b);
    __half al = __float2half_rn(a - __half2float(ah));
    __half bl = __float2half_rn(b - __half2float(bh));
    hi = (uint32_t)__half_as_ushort(ah) | ((uint32_t)__half_as_ushort(bh) << 16);
    lo = (uint32_t)__half_as_ushort(al) | ((uint32_t)__half_as_ushort(bl) << 16);
}

__device__ __forceinline__ uint32_t pack2h(float a, float b) {
    __half ah = __float2half_rn(a);
    __half bh = __float2half_rn(b);
    return (uint32_t)__half_as_ushort(ah) | ((uint32_t)__half_as_ushort(bh) << 16);
}

// ---------------- merged weight fp32 -> fp16 hi/lo (one launch) ----------------
#define CW_N0 393216
#define CW_N1 (CW_N0 + 131072)
#define CW_N2 (CW_N1 + 524288)
#define CW_N3 (CW_N2 + 524288)

__global__ __launch_bounds__(256) void cvtw_all_kernel(
    const float* __restrict__ s0, const float* __restrict__ s1,
    const float* __restrict__ s2, const float* __restrict__ s3,
    unsigned short* __restrict__ h0, unsigned short* __restrict__ l0,
    unsigned short* __restrict__ h1, unsigned short* __restrict__ l1,
    unsigned short* __restrict__ h2, unsigned short* __restrict__ l2,
    unsigned short* __restrict__ h3, unsigned short* __restrict__ l3)
{
    for (int i = blockIdx.x * blockDim.x + threadIdx.x; i < CW_N3;
         i += gridDim.x * blockDim.x) {
        const float* src; unsigned short *dh, *dl; int j;
        if (i < CW_N0)      { src = s0; dh = h0; dl = l0; j = i; }
        else if (i < CW_N1) { src = s1; dh = h1; dl = l1; j = i - CW_N0; }
        else if (i < CW_N2) { src = s2; dh = h2; dl = l2; j = i - CW_N1; }
        else                { src = s3; dh = h3; dl = l3; j = i - CW_N2; }
        float4 v0 = *(const float4*)(src + (size_t)j * 8);
        float4 v1 = *(const float4*)(src + (size_t)j * 8 + 4);
        uint4 h, l;
        cvt8h(v0, v1, h, l);
        ((uint4*)dh)[j] = h;
        ((uint4*)dl)[j] = l;
    }
}

// ---------------- LayerNorm -> fp16 hi only ----------------
__global__ __launch_bounds__(256) void ln_kernel(const float* __restrict__ x,
                                                 unsigned short* __restrict__ yh)
{
    int row = blockIdx.x;
    int tid = threadIdx.x;
    const float* xr = x + (size_t)row * E_DIM;

    float4 v = *(const float4*)(xr + tid * 4);
    float s  = v.x + v.y + v.z + v.w;
    float ss = v.x*v.x + v.y*v.y + v.z*v.z + v.w*v.w;

    #pragma unroll
    for (int off = 16; off > 0; off >>= 1) {
        s  += __shfl_xor_sync(0xffffffffu, s,  off);
        ss += __shfl_xor_sync(0xffffffffu, ss, off);
    }

    __shared__ float rs[8], rss[8], stat[2];
    int wid = tid >> 5, lane = tid & 31;
    if (lane == 0) { rs[wid] = s; rss[wid] = ss; }
    __syncthreads();
    if (tid == 0) {
        float t = 0.f, tt = 0.f;
        #pragma unroll
        for (int i = 0; i < 8; i++) { t += rs[i]; tt += rss[i]; }
        float mean = t * (1.0f / E_DIM);
        float var  = tt * (1.0f / E_DIM) - mean * mean;
        stat[0] = mean;
        stat[1] = rsqrtf(var + 1e-5f);
    }
    __syncthreads();
    float mean = stat[0], rstd = stat[1];
    uint2 hh;
    hh.x = pack2h((v.x - mean) * rstd, (v.y - mean) * rstd);
    hh.y = pack2h((v.z - mean) * rstd, (v.w - mean) * rstd);
    *(uint2*)(yh + (size_t)row * E_DIM + tid * 4) = hh;
}

// ================= fp16x2 GEMM: C = Ahi @ (Bhi + Blo)^T =================
// Tile 128x128, BK=16, 4-stage cp.async (3 tiles/stage: Ah, Bh, Bl).
#define F_BIAS  1
#define F_RELU  2
#define F_RES   4
#define F_OUTH  8     // write Ch (fp16 hi) only
#define F_OUTHL 16    // write Ch + Cl (fp16 hi/lo)

#define GB_TILE  6144               // 128 rows x 48 B
#define GB_STAGE (3 * GB_TILE)      // 18432
#define GB_SMEM  (4 * GB_STAGE)     // 73728; x2 CTAs = 147456 <= 228KB

template<int FLAGS>
__global__ __launch_bounds__(256, 2)
void gemm_f16_kernel(const unsigned short* __restrict__ Ah,
                     const unsigned short* __restrict__ Bh,
                     const unsigned short* __restrict__ Bl,
                     const float* __restrict__ bias, const float* __restrict__ res,
                     float* __restrict__ C,
                     unsigned short* __restrict__ Ch, unsigned short* __restrict__ Cl,
                     int M, int N, int K)
{
    extern __shared__ __align__(16) char smem[];
    uint32_t sb = smem_u32(smem);

    int tid = threadIdx.x;
    int lane = tid & 31, wid = tid >> 5;
    int wm = wid >> 1, wn = wid & 1;
    int bn = blockIdx.x, bm = blockIdx.y;

    int r0 = tid >> 1, c0 = tid & 1;
    uint32_t so = (uint32_t)(r0 * 48 + c0 * 16);
    size_t goff = (size_t)r0 * K + c0 * 8;
    const unsigned short* pA0 = Ah + (size_t)(bm * 128) * K + goff;
    const unsigned short* pB0 = Bh + (size_t)(bn * 128) * K + goff;
    const unsigned short* pX0 = Bl + (size_t)(bn * 128) * K + goff;

    uint32_t rpA = (uint32_t)((wm * 32 + (lane & 15)) * 48 + (lane >> 4) * 16);
    int g = lane >> 3, l8 = lane & 7;
    uint32_t rpB = (uint32_t)((wn * 64 + l8 + (g >> 1) * 8) * 48 + (g & 1) * 16);

    float acc[2][8][4];
    #pragma unroll
    for (int mt = 0; mt < 2; mt++)
        #pragma unroll
        for (int nt = 0; nt < 8; nt++)
            #pragma unroll
            for (int i = 0; i < 4; i++) acc[mt][nt][i] = 0.f;

    int nch = K >> 4;

    #define GB_ISSUE(kc) do {                                            \
        if ((kc) < nch) {                                                \
            uint32_t sa = sb + (uint32_t)((kc) & 3) * GB_STAGE;          \
            int off = (kc) * 16;                                         \
            CPA16(sa + so,               pA0 + off);                     \
            CPA16(sa + GB_TILE + so,     pB0 + off);                     \
            CPA16(sa + 2*GB_TILE + so,   pX0 + off);                     \
        }                                                                \
        CPC();                                                           \
    } while (0)

    GB_ISSUE(0);
    GB_ISSUE(1);
    GB_ISSUE(2);

    for (int kc = 0; kc < nch; kc++) {
        CPW(2);
        __syncthreads();

        uint32_t base = sb + (uint32_t)(kc & 3) * GB_STAGE;
        uint32_t aHi = base;
        uint32_t bHi = base + GB_TILE, bLo = base + 2*GB_TILE;

        uint32_t ah[8], bb[16];
        ldsm4(ah + 0, aHi + rpA);
        ldsm4(ah + 4, aHi + rpA + 768);     // +16 rows (16*48)
        #pragma unroll
        for (int i = 0; i < 4; i++)
            ldsm4(bb + i*4, bHi + rpB + (uint32_t)i*768);
        #pragma unroll
        for (int mt = 0; mt < 2; mt++)
            #pragma unroll
            for (int nt = 0; nt < 8; nt++)
                mma16816(acc[mt][nt], ah + mt*4, bb + nt*2);
        #pragma unroll
        for (int i = 0; i < 4; i++)
            ldsm4(bb + i*4, bLo + rpB + (uint32_t)i*768);
        #pragma unroll
        for (int mt = 0; mt < 2; mt++)
            #pragma unroll
            for (int nt = 0; nt < 8; nt++)
                mma16816(acc[mt][nt], ah + mt*4, bb + nt*2);

        GB_ISSUE(kc + 3);
    }
    #undef GB_ISSUE

    // ---- epilogue ----
    #pragma unroll
    for (int mt = 0; mt < 2; mt++) {
        int gr0 = bm*128 + wm*32 + mt*16 + (lane >> 2);
        #pragma unroll
        for (int nt = 0; nt < 8; nt++) {
            int gc = bn*128 + wn*64 + nt*8 + (lane & 3)*2;
            #pragma unroll
            for (int hfl = 0; hfl < 2; hfl++) {
                int row = gr0 + hfl*8;
                float v0 = acc[mt][nt][hfl*2+0];
                float v1 = acc[mt][nt][hfl*2+1];
                if (FLAGS & F_BIAS) {
                    v0 += __ldg(bias + gc);
                    v1 += __ldg(bias + gc + 1);
                }
                if (FLAGS & F_RES) {
                    float2 rr = *(const float2*)(res + (size_t)row * N + gc);
                    v0 += rr.x; v1 += rr.y;
                }
                if (FLAGS & F_RELU) { v0 = fmaxf(v0, 0.f); v1 = fmaxf(v1, 0.f); }
                if (FLAGS & F_OUTHL) {
                    uint32_t h, l;
                    packhl_h(v0, v1, h, l);
                    *(uint32_t*)(Ch + (size_t)row * N + gc) = h;
                    *(uint32_t*)(Cl + (size_t)row * N + gc) = l;
                } else if (FLAGS & F_OUTH) {
                    *(uint32_t*)(Ch + (size_t)row * N + gc) = pack2h(v0, v1);
                } else {
                    float2 o = make_float2(v0, v1);
                    *(float2*)(C + (size_t)row * N + gc) = o;
                }
            }
        }
    }
}

// ================= Flash attention: fp16x2, cp.async 3-stage, occ 2 =================
// Q hi-only in registers; K/V hi+lo in pipeline stages. P hi-only.
#define FST_TIL  9216                 // 64*144
#define FST_STG  (4 * FST_TIL)        // 36864
#define FST_SMEM (3 * FST_STG)        // 110592; x2 CTAs = 221184 <= 228KB

__global__ __launch_bounds__(256, 2)
void flash_mma_kernel(const unsigned short* __restrict__ qh_g,
                      const unsigned short* __restrict__ ql_g,
                      unsigned short* __restrict__ oh)
{
    extern __shared__ __align__(16) char smf[];
    uint32_t sb  = smem_u32(smf);

    int tid = threadIdx.x, lane = tid & 31, wid = tid >> 5;
    int qi = (int)gridDim.x - 1 - (int)blockIdx.x;   // longest CTAs first
    int bh = blockIdx.y;
    int b = bh >> 4, h = bh & 15;

    const int QKV_W = 3 * E_DIM;   // 3072
    size_t rowbase = (size_t)b * S_DIM;

    // ---- stage Q hi through stage-0 smem, build register fragments ----
    {
        int r = tid >> 1, ce = (tid & 1) * 32;
        const unsigned short* sh = qh_g + (rowbase + qi*128 + r) * QKV_W + h*64 + ce;
        uint32_t d = sb + (uint32_t)(r*144 + ce*2);
        #pragma unroll
        for (int k = 0; k < 4; k++)
            CPA16(d + k*16, sh + k*8);
        CPC(); CPW(0);
    }
    __syncthreads();

    uint32_t qh[4][4];
    {
        uint32_t ra = sb + (uint32_t)((wid*16 + (lane & 15))*144 + (lane >> 4)*16);
        #pragma unroll
        for (int ks = 0; ks < 4; ks++)
            ldsm4(qh[ks], ra + ks*32);
    }
    __syncthreads();   // Q staging done before pipeline overwrites stage 0

    float oacc[8][4];
    #pragma unroll
    for (int nt = 0; nt < 8; nt++)
        #pragma unroll
        for (int i = 0; i < 4; i++) oacc[nt][i] = 0.f;
    float rm0 = -1e30f, rm1 = -1e30f, rl0 = 0.f, rl1 = 0.f;

    int g = lane >> 3, l8 = lane & 7;
    uint32_t rpB = (uint32_t)((l8 + (g >> 1)*8)*144 + (g & 1)*16);
    uint32_t rpV = (uint32_t)((lane & 15)*144 + (lane >> 4)*16);

    int rowlim = qi*128 + wid*16 + 15;
    int nj = 2*qi + 2;

    int rkv = tid >> 2, ckv = tid & 3;
    uint32_t skv = (uint32_t)(rkv*144 + ckv*32);
    const unsigned short* kh0 = qh_g + (rowbase + rkv) * QKV_W + E_DIM   + h*64 + ckv*16;
    const unsigned short* kl0 = ql_g + (rowbase + rkv) * QKV_W + E_DIM   + h*64 + ckv*16;
    const unsigned short* vh0 = qh_g + (rowbase + rkv) * QKV_W + 2*E_DIM + h*64 + ckv*16;
    const unsigned short* vl0 = ql_g + (rowbase + rkv) * QKV_W + 2*E_DIM + h*64 + ckv*16;

    #define FS_ISSUE(jt) do {                                              \
        if ((jt) < nj) {                                                   \
            uint32_t sg = sb + (uint32_t)((jt) % 3) * FST_STG;             \
            size_t off = (size_t)(jt) * 64 * QKV_W;                        \
            CPA16(sg + skv,                  kh0 + off);                   \
            CPA16(sg + skv + 16,             kh0 + off + 8);               \
            CPA16(sg + FST_TIL + skv,        kl0 + off);                   \
            CPA16(sg + FST_TIL + skv + 16,   kl0 + off + 8);               \
            CPA16(sg + 2*FST_TIL + skv,      vh0 + off);                   \
            CPA16(sg + 2*FST_TIL + skv + 16, vh0 + off + 8);               \
            CPA16(sg + 3*FST_TIL + skv,      vl0 + off);                   \
            CPA16(sg + 3*FST_TIL + skv + 16, vl0 + off + 8);               \
        }                                                                  \
        CPC();                                                             \
    } while (0)

    FS_ISSUE(0);
    FS_ISSUE(1);

    for (int jt = 0; jt < nj; jt++) {
        CPW(1);
        __syncthreads();
        FS_ISSUE(jt + 2);

        if (jt*64 > rowlim) continue;

        uint32_t Khi = sb + (uint32_t)(jt % 3) * FST_STG;
        uint32_t Klo = Khi + FST_TIL;
        uint32_t Vhi = Khi + 2*FST_TIL;
        uint32_t Vlo = Khi + 3*FST_TIL;

        // ---- S = Qhi (Khi + Klo)^T, then *0.125 ----
        float s[8][4];
        #pragma unroll
        for (int nt = 0; nt < 8; nt++)
            #pragma unroll
            for (int i = 0; i < 4; i++) s[nt][i] = 0.f;
        {
            uint32_t kb[16];
            #pragma unroll
            for (int ks = 0; ks < 4; ks++) {
                #pragma unroll
                for (int i = 0; i < 4; i++)
                    ldsm4(kb + 4*i, Khi + rpB + (uint32_t)i*2304 + ks*32);
                #pragma unroll
                for (int nt = 0; nt < 8; nt++)
                    mma16816(s[nt], qh[ks], kb + 2*nt);
                #pragma unroll
                for (int i = 0; i < 4; i++)
                    ldsm4(kb + 4*i, Klo + rpB + (uint32_t)i*2304 + ks*32);
                #pragma unroll
                for (int nt = 0; nt < 8; nt++)
                    mma16816(s[nt], qh[ks], kb + 2*nt);
            }
        }
        #pragma unroll
        for (int nt = 0; nt < 8; nt++)
            #pragma unroll
            for (int i = 0; i < 4; i++) s[nt][i] *= 0.125f;

        int row0 = qi*128 + wid*16 + (lane >> 2);
        if (jt >= 2*qi) {
            #pragma unroll
            for (int nt = 0; nt < 8; nt++) {
                int col = jt*64 + nt*8 + (lane & 3)*2;
                if (col     > row0)     s[nt][0] = -1e30f;
                if (col + 1 > row0)     s[nt][1] = -1e30f;
                if (col     > row0 + 8) s[nt][2] = -1e30f;
                if (col + 1 > row0 + 8) s[nt][3] = -1e30f;
            }
        }

        float m0 = -1e30f, m1 = -1e30f;
        #pragma unroll
        for (int nt = 0; nt < 8; nt++) {
            m0 = fmaxf(m0, fmaxf(s[nt][0], s[nt][1]));
            m1 = fmaxf(m1, fmaxf(s[nt][2], s[nt][3]));
        }
        m0 = fmaxf(m0, __shfl_xor_sync(0xffffffffu, m0, 1));
        m0 = fmaxf(m0, __shfl_xor_sync(0xffffffffu, m0, 2));
        m1 = fmaxf(m1, __shfl_xor_sync(0xffffffffu, m1, 1));
        m1 = fmaxf(m1, __shfl_xor_sync(0xffffffffu, m1, 2));

        float mn0 = fmaxf(rm0, m0), mn1 = fmaxf(rm1, m1);
        float al0 = __expf(rm0 - mn0), al1 = __expf(rm1 - mn1);
        rm0 = mn0; rm1 = mn1;

        float sum0 = 0.f, sum1 = 0.f;
        #pragma unroll
        for (int nt = 0; nt < 8; nt++) {
            s[nt][0] = __expf(s[nt][0] - mn0);
            s[nt][1] = __expf(s[nt][1] - mn0);
            s[nt][2] = __expf(s[nt][2] - mn1);
            s[nt][3] = __expf(s[nt][3] - mn1);
            sum0 += s[nt][0] + s[nt][1];
            sum1 += s[nt][2] + s[nt][3];
        }
        sum0 += __shfl_xor_sync(0xffffffffu, sum0, 1);
        sum0 += __shfl_xor_sync(0xffffffffu, sum0, 2);
        sum1 += __shfl_xor_sync(0xffffffffu, sum1, 1);
        sum1 += __shfl_xor_sync(0xffffffffu, sum1, 2);
        rl0 = rl0 * al0 + sum0;
        rl1 = rl1 * al1 + sum1;

        #pragma unroll
        for (int nt = 0; nt < 8; nt++) {
            oacc[nt][0] *= al0; oacc[nt][1] *= al0;
            oacc[nt][2] *= al1; oacc[nt][3] *= al1;
        }

        // ---- P fragments (hi only) ----
        uint32_t ph[4][4];
        #pragma unroll
        for (int ks = 0; ks < 4; ks++) {
            int j0 = 2*ks, j1 = 2*ks + 1;
            ph[ks][0] = pack2h(s[j0][0], s[j0][1]);
            ph[ks][1] = pack2h(s[j0][2], s[j0][3]);
            ph[ks][2] = pack2h(s[j1][0], s[j1][1]);
            ph[ks][3] = pack2h(s[j1][2], s[j1][3]);
        }

        // ---- O += Phi (Vhi + Vlo) ----
        {
            uint32_t vb[16];
            #pragma unroll
            for (int ks = 0; ks < 4; ks++) {
                #pragma unroll
                for (int i = 0; i < 4; i++)
                    ldsm4t(vb + 4*i, Vhi + rpV + (uint32_t)ks*2304 + (uint32_t)i*32);
                #pragma unroll
                for (int nt = 0; nt < 8; nt++)
                    mma16816(oacc[nt], ph[ks], vb + 2*nt);
                #pragma unroll
                for (int i = 0; i < 4; i++)
                    ldsm4t(vb + 4*i, Vlo + rpV + (uint32_t)ks*2304 + (uint32_t)i*32);
                #pragma unroll
                for (int nt = 0; nt < 8; nt++)
                    mma16816(oacc[nt], ph[ks], vb + 2*nt);
            }
        }
    }
    #undef FS_ISSUE

    // ---- epilogue: normalize, write fp16 hi ----
    float inv0 = 1.0f / rl0, inv1 = 1.0f / rl1;
    int row0 = qi*128 + wid*16 + (lane >> 2);
    size_t obase = (size_t)b * S_DIM * E_DIM + h * 64;
    #pragma unroll
    for (int nt = 0; nt < 8; nt++) {
        int col = nt*8 + (lane & 3)*2;
        *(uint32_t*)(oh + obase + (size_t)row0       * E_DIM + col) =
            pack2h(oacc[nt][0]*inv0, oacc[nt][1]*inv0);
        *(uint32_t*)(oh + obase + (size_t)(row0 + 8) * E_DIM + col) =
            pack2h(oacc[nt][2]*inv1, oacc[nt][3]*inv1);
    }
}

// ---------------- launch ----------------
extern "C" void kernel_launch(void* const* d_in, const int* in_sizes, int n_in,
                              void* d_out, int out_size)
{
    const float* x      = (const float*)d_in[0];
    const float* w_in   = (const float*)d_in[1];
    const float* w_out  = (const float*)d_in[2];
    const float* w_fc   = (const float*)d_in[3];
    const float* b_fc   = (const float*)d_in[4];
    const float* w_proj = (const float*)d_in[5];
    const float* b_proj = (const float*)d_in[6];
    float* out = (float*)d_out;

    void *px2, *phh, *pqh, *pql, *poh, *pmh;
    void *pwinh, *pwinl, *pwouth, *pwoutl, *pwfch, *pwfcl, *pwprh, *pwprl;
    cudaGetSymbolAddress(&px2,  g_x2);
    cudaGetSymbolAddress(&phh,  g_hh);
    cudaGetSymbolAddress(&pqh,  g_qkvh); cudaGetSymbolAddress(&pql,  g_qkvl);
    cudaGetSymbolAddress(&poh,  g_oh);
    cudaGetSymbolAddress(&pmh,  g_mh);
    cudaGetSymbolAddress(&pwinh,  g_winh);  cudaGetSymbolAddress(&pwinl,  g_winl);
    cudaGetSymbolAddress(&pwouth, g_wouth); cudaGetSymbolAddress(&pwoutl, g_woutl);
    cudaGetSymbolAddress(&pwfch,  g_wfch);  cudaGetSymbolAddress(&pwfcl,  g_wfcl);
    cudaGetSymbolAddress(&pwprh,  g_wprh);  cudaGetSymbolAddress(&pwprl,  g_wprl);

    float* bx2  = (float*)px2;
    unsigned short *bhh = (unsigned short*)phh;
    unsigned short *bqh = (unsigned short*)pqh, *bql = (unsigned short*)pql;
    unsigned short *boh = (unsigned short*)poh;
    unsigned short *bmh = (unsigned short*)pmh;
    unsigned short *winh = (unsigned short*)pwinh, *winl = (unsigned short*)pwinl;
    unsigned short *wouth = (unsigned short*)pwouth, *woutl = (unsigned short*)pwoutl;
    unsigned short *wfch = (unsigned short*)pwfch, *wfcl = (unsigned short*)pwfcl;
    unsigned short *wprh = (unsigned short*)pwprh, *wprl = (unsigned short*)pwprl;

    cudaFuncSetAttribute(flash_mma_kernel,
                         cudaFuncAttributeMaxDynamicSharedMemorySize, FST_SMEM);
    cudaFuncSetAttribute(gemm_f16_kernel<F_OUTHL>,
                         cudaFuncAttributeMaxDynamicSharedMemorySize, GB_SMEM);
    cudaFuncSetAttribute(gemm_f16_kernel<F_RES>,
                         cudaFuncAttributeMaxDynamicSharedMemorySize, GB_SMEM);
    cudaFuncSetAttribute(gemm_f16_kernel<F_BIAS|F_RELU|F_OUTH>,
                         cudaFuncAttributeMaxDynamicSharedMemorySize, GB_SMEM);
    cudaFuncSetAttribute(gemm_f16_kernel<F_BIAS|F_RES>,
                         cudaFuncAttributeMaxDynamicSharedMemorySize, GB_SMEM);

    // 0) weight conversions (single launch)
    cvtw_all_kernel<<<1536, 256>>>(w_in, w_out, w_fc, w_proj,
                                   winh, winl, wouth, woutl,
                                   wfch, wfcl, wprh, wprl);

    // 1) h = LN(x) -> fp16 hi
    ln_kernel<<<NROWS, 256>>>(x, bhh);
    // 2) qkv = h @ w_in^T -> fp16 hi+lo (lo needed for K/V B-operand roles)
    gemm_f16_kernel<F_OUTHL><<<dim3(3072/128, NROWS/128), 256, GB_SMEM>>>(
        bhh, winh, winl, nullptr, nullptr, nullptr, bqh, bql,
        NROWS, 3072, 1024);
    // 3) o = causal attention(qkv) -> fp16 hi
    flash_mma_kernel<<<dim3(S_DIM/128, B_DIM*H_DIM), 256, FST_SMEM>>>(
        bqh, bql, boh);
    // 4) x2 = o @ w_out^T + x   (fp32)
    gemm_f16_kernel<F_RES><<<dim3(1024/128, NROWS/128), 256, GB_SMEM>>>(
        boh, wouth, woutl, nullptr, x, bx2, nullptr, nullptr,
        NROWS, 1024, 1024);
    // 5) h2 = LN(x2) -> fp16 hi
    ln_kernel<<<NROWS, 256>>>(bx2, bhh);
    // 6) m = relu(h2 @ w_fc^T + b_fc) -> fp16 hi
    gemm_f16_kernel<F_BIAS|F_RELU|F_OUTH><<<dim3(4096/128, NROWS/128), 256, GB_SMEM>>>(
        bhh, wfch, wfcl, b_fc, nullptr, nullptr, bmh, nullptr,
        NROWS, 4096, 1024);
    // 7) out = m @ w_proj^T + b_proj + x2   (fp32)
    gemm_f16_kernel<F_BIAS|F_RES><<<dim3(1024/128, NROWS/128), 256, GB_SMEM>>>(
        bmh, wprh, wprl, b_proj, bx2, out, nullptr, nullptr,
        NROWS, 1024, 4096);
}